// round 4
// baseline (speedup 1.0000x reference)
#include <cuda_runtime.h>

#define DIM_B 4096
#define DIM_M 128
#define DIM_C 128
#define DIM_Q 256
#define WB    1024      // batches per L2 wave (~67 MB valid data < 126 MB L2)
#define NWAVES (DIM_B / WB)
#define VGB   8         // batches per block in vgemm

// ---- scratch (static device globals: no allocation allowed) ----
__device__ float g_T1[DIM_Q * DIM_C];     // Wk^T @ Wc^T   (256 x 128)
__device__ float g_W [DIM_Q * DIM_Q];     // combined weight (256 x 256)
__device__ float g_xsum[DIM_B * DIM_Q];   // masked row sums (4 MB)
__device__ float g_v  [DIM_B * DIM_Q];    // per-batch query vectors (4 MB)
__device__ int   g_base[DIM_B];           // exclusive prefix sum of lens
__device__ int   g_sh_len;                // 0 = int32 seq_lengths, 1 = int64

typedef unsigned long long ull;

__device__ __forceinline__ ull pack2(float lo, float hi) {
    ull r; asm("mov.b64 %0, {%1, %2};" : "=l"(r) : "f"(lo), "f"(hi)); return r;
}
__device__ __forceinline__ void unpack2(ull v, float& lo, float& hi) {
    asm("mov.b64 {%0, %1}, %2;" : "=f"(lo), "=f"(hi) : "l"(v));
}
__device__ __forceinline__ ull fma2(ull a, ull b, ull c) {
    ull d; asm("fma.rn.f32x2 %0, %1, %2, %3;" : "=l"(d) : "l"(a), "l"(b), "l"(c)); return d;
}

// ---- K0: dtype detect + exclusive prefix scan of seq_lengths ----
// lens[1] = 38: int32 word[1] != 0; if int64, word[1] = high half of lens[0] = 0.
__global__ void scan_kernel(const int* __restrict__ seq) {
    int sh = (seq[1] == 0) ? 1 : 0;
    if (threadIdx.x == 0) g_sh_len = sh;

    __shared__ int cs[1024], cs2[1024];
    int t = threadIdx.x;              // 1024 threads, 4 lens each
    int l[4]; int sum = 0;
#pragma unroll
    for (int i = 0; i < 4; i++) {
        l[i] = seq[(size_t)(4 * t + i) << sh];
        sum += l[i];
    }
    cs[t] = sum;
    __syncthreads();
    int* src = cs; int* dst = cs2;
    for (int off = 1; off < 1024; off <<= 1) {
        int v = src[t];
        if (t >= off) v += src[t - off];
        dst[t] = v;
        __syncthreads();
        int* tmp = src; src = dst; dst = tmp;
    }
    int run = (t > 0) ? src[t - 1] : 0;   // exclusive chunk base
#pragma unroll
    for (int i = 0; i < 4; i++) {
        g_base[4 * t + i] = run;
        run += l[i];
    }
}

// ---- K0a: T1[q][m] = sum_c Wk[c][q] * Wc[m][c] ----
__global__ void t1_kernel(const float* __restrict__ Wk, const float* __restrict__ Wc) {
    int q = blockIdx.x;      // 0..255
    int m = threadIdx.x;     // 0..127
    float s = 0.f;
#pragma unroll 4
    for (int c = 0; c < DIM_C; c++)
        s = fmaf(Wk[c * DIM_Q + q], Wc[m * DIM_C + c], s);
    g_T1[q * DIM_C + m] = s;
}

// ---- K0b: W[q][q'] = sum_m T1[q][m] * proj[m][q'] ----
__global__ void wcomb_kernel(const float* __restrict__ proj) {
    int q  = blockIdx.x;     // 0..255
    int qp = threadIdx.x;    // 0..255
    float s = 0.f;
#pragma unroll 4
    for (int m = 0; m < DIM_M; m++)
        s = fmaf(g_T1[q * DIM_M + m], proj[m * DIM_Q + qp], s);
    g_W[q * DIM_Q + qp] = s;
}

// ---- K1: xsum[b][q] = sum_{m < len[b]} xss[b][m][q]  (block per batch) ----
// Default cache policy on purpose: the upcoming y pass re-reads this wave from L2.
__global__ void xsum_kernel(const float* __restrict__ xss, const int* __restrict__ seq,
                            int b0) {
    int b   = b0 + blockIdx.x;
    int len = seq[(size_t)b << g_sh_len];
    int t   = threadIdx.x;           // 256 threads
    int q4  = t & 63;                // float4 column
    int mg  = t >> 6;                // row group 0..3
    const float4* base = (const float4*)xss + (size_t)b * (DIM_M * DIM_Q / 4);
    float4 acc = make_float4(0.f, 0.f, 0.f, 0.f);
#pragma unroll 4
    for (int m = mg; m < len; m += 4) {
        float4 v = base[m * (DIM_Q / 4) + q4];
        acc.x += v.x; acc.y += v.y; acc.z += v.z; acc.w += v.w;
    }
    __shared__ float4 red[4][64];
    red[mg][q4] = acc;
    __syncthreads();
    if (t < 64) {
        float4 a = red[0][t], c = red[1][t], d = red[2][t], e = red[3][t];
        float4 s;
        s.x = (a.x + c.x) + (d.x + e.x);
        s.y = (a.y + c.y) + (d.y + e.y);
        s.z = (a.z + c.z) + (d.z + e.z);
        s.w = (a.w + c.w) + (d.w + e.w);
        ((float4*)(g_xsum + (size_t)b * DIM_Q))[t] = s;
    }
}

// ---- K2: v = xsum @ W for one wave (8 batches / 256-thread block) ----
__global__ void vgemm_kernel(int b0) {
    __shared__ float xsT[DIM_Q][VGB];   // [q][g]
    int t  = threadIdx.x;               // 0..255
    int bb = b0 + blockIdx.x * VGB;
    for (int idx = t; idx < VGB * DIM_Q; idx += 256) {
        int g = idx >> 8;
        int q = idx & 255;
        xsT[q][g] = g_xsum[(size_t)(bb + g) * DIM_Q + q];
    }
    __syncthreads();
    ull acc2[VGB / 2];
#pragma unroll
    for (int j = 0; j < VGB / 2; j++) acc2[j] = 0ull;

    for (int q = 0; q < DIM_Q; q++) {
        float w = g_W[q * DIM_Q + t];            // coalesced, L2-resident
        ull wp = pack2(w, w);
        const ull* xp = (const ull*)&xsT[q][0];  // broadcast reads
#pragma unroll
        for (int j = 0; j < VGB / 2; j++)
            acc2[j] = fma2(xp[j], wp, acc2[j]);
    }
#pragma unroll
    for (int j = 0; j < VGB / 2; j++) {
        float lo, hi;
        unpack2(acc2[j], lo, hi);
        g_v[(size_t)(bb + 2 * j)     * DIM_Q + t] = lo;
        g_v[(size_t)(bb + 2 * j + 1) * DIM_Q + t] = hi;
    }
}

// ---- K3: y, block-per-batch; rows should be L2-resident from the xsum pass ----
__global__ void y_kernel(const float* __restrict__ xss, const int* __restrict__ seq,
                         float* __restrict__ out, int b0) {
    int b    = b0 + blockIdx.x;
    int len  = seq[(size_t)b << g_sh_len];
    int base = g_base[b];
    int t    = threadIdx.x;          // 256
    int w    = t >> 5, lane = t & 31;

    const float4* vr = (const float4*)(g_v + (size_t)b * DIM_Q);
    float4 v0 = vr[lane];
    float4 v1 = vr[lane + 32];

    const float4* xb = (const float4*)(xss + (size_t)b * DIM_M * DIM_Q);

    int m = w;
    for (; m + 8 < len; m += 16) {
        float4 a0 = xb[(size_t)m * 64 + lane];
        float4 a1 = xb[(size_t)m * 64 + 32 + lane];
        float4 c0 = xb[(size_t)(m + 8) * 64 + lane];
        float4 c1 = xb[(size_t)(m + 8) * 64 + 32 + lane];
        float s0 = 0.f, s1 = 0.f;
        s0 = fmaf(a0.x, v0.x, s0); s0 = fmaf(a0.y, v0.y, s0);
        s0 = fmaf(a0.z, v0.z, s0); s0 = fmaf(a0.w, v0.w, s0);
        s0 = fmaf(a1.x, v1.x, s0); s0 = fmaf(a1.y, v1.y, s0);
        s0 = fmaf(a1.z, v1.z, s0); s0 = fmaf(a1.w, v1.w, s0);
        s1 = fmaf(c0.x, v0.x, s1); s1 = fmaf(c0.y, v0.y, s1);
        s1 = fmaf(c0.z, v0.z, s1); s1 = fmaf(c0.w, v0.w, s1);
        s1 = fmaf(c1.x, v1.x, s1); s1 = fmaf(c1.y, v1.y, s1);
        s1 = fmaf(c1.z, v1.z, s1); s1 = fmaf(c1.w, v1.w, s1);
#pragma unroll
        for (int off = 16; off > 0; off >>= 1) {
            s0 += __shfl_xor_sync(0xffffffffu, s0, off);
            s1 += __shfl_xor_sync(0xffffffffu, s1, off);
        }
        if (lane == 0) {
            out[base + m]     = s0;
            out[base + m + 8] = s1;
        }
    }
    if (m < len) {
        float4 a0 = xb[(size_t)m * 64 + lane];
        float4 a1 = xb[(size_t)m * 64 + 32 + lane];
        float s0 = 0.f;
        s0 = fmaf(a0.x, v0.x, s0); s0 = fmaf(a0.y, v0.y, s0);
        s0 = fmaf(a0.z, v0.z, s0); s0 = fmaf(a0.w, v0.w, s0);
        s0 = fmaf(a1.x, v1.x, s0); s0 = fmaf(a1.y, v1.y, s0);
        s0 = fmaf(a1.z, v1.z, s0); s0 = fmaf(a1.w, v1.w, s0);
#pragma unroll
        for (int off = 16; off > 0; off >>= 1)
            s0 += __shfl_xor_sync(0xffffffffu, s0, off);
        if (lane == 0) out[base + m] = s0;
    }
}

extern "C" void kernel_launch(void* const* d_in, const int* in_sizes, int n_in,
                              void* d_out, int out_size) {
    const float* xss  = (const float*)d_in[0];
    const float* Wk   = (const float*)d_in[1];
    const float* Wc   = (const float*)d_in[2];
    const float* proj = (const float*)d_in[3];
    const int*   seq  = (const int*)d_in[4];
    float* out = (float*)d_out;

    scan_kernel<<<1, 1024>>>(seq);
    t1_kernel<<<DIM_Q, DIM_C>>>(Wk, Wc);
    wcomb_kernel<<<DIM_Q, DIM_Q>>>(proj);

    // L2 wave blocking: xsum pulls a wave into L2; y re-reads it from L2.
    for (int w = 0; w < NWAVES; w++) {
        int b0 = w * WB;
        xsum_kernel<<<WB, 256>>>(xss, seq, b0);
        vgemm_kernel<<<WB / VGB, 256>>>(b0);
        y_kernel<<<WB, 256>>>(xss, seq, out, b0);
    }
}

// round 5
// speedup vs baseline: 1.6052x; 1.6052x over previous
#include <cuda_runtime.h>

#define DIM_B 4096
#define DIM_M 128
#define DIM_C 128
#define DIM_Q 256
#define VGB   8         // batches per block in vgemm

// ---- scratch (static device globals: no allocation allowed) ----
__device__ float g_W [DIM_Q * DIM_Q];     // combined weight (256 x 256)
__device__ float g_xsum[DIM_B * DIM_Q];   // masked row sums (4 MB)
__device__ float g_v  [DIM_B * DIM_Q];    // per-batch query vectors (4 MB)
__device__ int   g_base[DIM_B];           // exclusive prefix sum of lens
__device__ int   g_sh_len;                // 0 = int32 seq_lengths, 1 = int64

typedef unsigned long long ull;

__device__ __forceinline__ ull pack2(float lo, float hi) {
    ull r; asm("mov.b64 %0, {%1, %2};" : "=l"(r) : "f"(lo), "f"(hi)); return r;
}
__device__ __forceinline__ void unpack2(ull v, float& lo, float& hi) {
    asm("mov.b64 {%0, %1}, %2;" : "=f"(lo), "=f"(hi) : "l"(v));
}
__device__ __forceinline__ ull fma2(ull a, ull b, ull c) {
    ull d; asm("fma.rn.f32x2 %0, %1, %2, %3;" : "=l"(d) : "l"(a), "l"(b), "l"(c)); return d;
}

// ---- K0: dtype detect + exclusive prefix scan of seq_lengths ----
// lens[1] = 38: int32 word[1] != 0; if int64, word[1] = high half of lens[0] = 0.
__global__ void scan_kernel(const int* __restrict__ seq) {
    int sh = (seq[1] == 0) ? 1 : 0;
    if (threadIdx.x == 0) g_sh_len = sh;

    __shared__ int cs[1024], cs2[1024];
    int t = threadIdx.x;              // 1024 threads, 4 lens each
    int l[4]; int sum = 0;
#pragma unroll
    for (int i = 0; i < 4; i++) {
        l[i] = seq[(size_t)(4 * t + i) << sh];
        sum += l[i];
    }
    cs[t] = sum;
    __syncthreads();
    int* src = cs; int* dst = cs2;
    for (int off = 1; off < 1024; off <<= 1) {
        int v = src[t];
        if (t >= off) v += src[t - off];
        dst[t] = v;
        __syncthreads();
        int* tmp = src; src = dst; dst = tmp;
    }
    int run = (t > 0) ? src[t - 1] : 0;   // exclusive chunk base
#pragma unroll
    for (int i = 0; i < 4; i++) {
        g_base[4 * t + i] = run;
        run += l[i];
    }
}

// ---- K0a: fused W = (Wk^T Wc^T) @ proj. Block q computes row W[q][:]. ----
__global__ void wcomb_kernel(const float* __restrict__ Wk, const float* __restrict__ Wc,
                             const float* __restrict__ proj) {
    __shared__ float t1[DIM_M];       // T1[q][m] for this q
    int q = blockIdx.x;               // 0..255
    int t = threadIdx.x;              // 0..127
    float s = 0.f;
#pragma unroll 4
    for (int c = 0; c < DIM_C; c++)
        s = fmaf(Wk[c * DIM_Q + q], Wc[t * DIM_C + c], s);
    t1[t] = s;
    __syncthreads();
    float s0 = 0.f, s1 = 0.f;
#pragma unroll 4
    for (int m = 0; m < DIM_M; m++) {
        float a = t1[m];
        s0 = fmaf(a, proj[m * DIM_Q + t], s0);
        s1 = fmaf(a, proj[m * DIM_Q + 128 + t], s1);
    }
    g_W[q * DIM_Q + t]       = s0;
    g_W[q * DIM_Q + 128 + t] = s1;
}

// ---- K1: xsum[b][q] = sum_{m < len[b]} xss[b][m][q]  (block per batch) ----
__global__ void xsum_kernel(const float* __restrict__ xss, const int* __restrict__ seq) {
    int b   = blockIdx.x;
    int len = seq[(size_t)b << g_sh_len];
    int t   = threadIdx.x;           // 256 threads
    int q4  = t & 63;                // float4 column
    int mg  = t >> 6;                // row group 0..3
    const float4* base = (const float4*)xss + (size_t)b * (DIM_M * DIM_Q / 4);
    float4 acc = make_float4(0.f, 0.f, 0.f, 0.f);
#pragma unroll 4
    for (int m = mg; m < len; m += 4) {
        float4 v = base[m * (DIM_Q / 4) + q4];
        acc.x += v.x; acc.y += v.y; acc.z += v.z; acc.w += v.w;
    }
    __shared__ float4 red[4][64];
    red[mg][q4] = acc;
    __syncthreads();
    if (t < 64) {
        float4 a = red[0][t], c = red[1][t], d = red[2][t], e = red[3][t];
        float4 s;
        s.x = (a.x + c.x) + (d.x + e.x);
        s.y = (a.y + c.y) + (d.y + e.y);
        s.z = (a.z + c.z) + (d.z + e.z);
        s.w = (a.w + c.w) + (d.w + e.w);
        ((float4*)(g_xsum + (size_t)b * DIM_Q))[t] = s;
    }
}

// ---- K2: v = xsum @ W  (8 batches per 256-thread block) ----
__global__ void vgemm_kernel() {
    __shared__ float xsT[DIM_Q][VGB];   // [q][g]
    int t  = threadIdx.x;               // 0..255
    int bb = blockIdx.x * VGB;
    for (int idx = t; idx < VGB * DIM_Q; idx += 256) {
        int g = idx >> 8;
        int q = idx & 255;
        xsT[q][g] = g_xsum[(size_t)(bb + g) * DIM_Q + q];
    }
    __syncthreads();
    ull acc2[VGB / 2];
#pragma unroll
    for (int j = 0; j < VGB / 2; j++) acc2[j] = 0ull;

    for (int q = 0; q < DIM_Q; q++) {
        float w = g_W[q * DIM_Q + t];            // coalesced, L2-resident
        ull wp = pack2(w, w);
        const ull* xp = (const ull*)&xsT[q][0];  // broadcast reads
#pragma unroll
        for (int j = 0; j < VGB / 2; j++)
            acc2[j] = fma2(xp[j], wp, acc2[j]);
    }
#pragma unroll
    for (int j = 0; j < VGB / 2; j++) {
        float lo, hi;
        unpack2(acc2[j], lo, hi);
        g_v[(size_t)(bb + 2 * j)     * DIM_Q + t] = lo;
        g_v[(size_t)(bb + 2 * j + 1) * DIM_Q + t] = hi;
    }
}

// ---- K3: y, block-per-batch, REVERSED batch order so the first-scheduled
// y blocks re-read the tail of xsum's stream while it is still L2-resident. ----
__global__ void y_kernel(const float* __restrict__ xss, const int* __restrict__ seq,
                         float* __restrict__ out) {
    int b    = (DIM_B - 1) - blockIdx.x;
    int len  = seq[(size_t)b << g_sh_len];
    int base = g_base[b];
    int t    = threadIdx.x;          // 256
    int w    = t >> 5, lane = t & 31;

    const float4* vr = (const float4*)(g_v + (size_t)b * DIM_Q);
    float4 v0 = vr[lane];
    float4 v1 = vr[lane + 32];

    const float4* xb = (const float4*)(xss + (size_t)b * DIM_M * DIM_Q);

    int m = w;
    for (; m + 8 < len; m += 16) {
        float4 a0 = xb[(size_t)m * 64 + lane];
        float4 a1 = xb[(size_t)m * 64 + 32 + lane];
        float4 c0 = xb[(size_t)(m + 8) * 64 + lane];
        float4 c1 = xb[(size_t)(m + 8) * 64 + 32 + lane];
        float s0 = 0.f, s1 = 0.f;
        s0 = fmaf(a0.x, v0.x, s0); s0 = fmaf(a0.y, v0.y, s0);
        s0 = fmaf(a0.z, v0.z, s0); s0 = fmaf(a0.w, v0.w, s0);
        s0 = fmaf(a1.x, v1.x, s0); s0 = fmaf(a1.y, v1.y, s0);
        s0 = fmaf(a1.z, v1.z, s0); s0 = fmaf(a1.w, v1.w, s0);
        s1 = fmaf(c0.x, v0.x, s1); s1 = fmaf(c0.y, v0.y, s1);
        s1 = fmaf(c0.z, v0.z, s1); s1 = fmaf(c0.w, v0.w, s1);
        s1 = fmaf(c1.x, v1.x, s1); s1 = fmaf(c1.y, v1.y, s1);
        s1 = fmaf(c1.w, v1.w, s1); s1 = fmaf(c1.z, v1.z, s1);
#pragma unroll
        for (int off = 16; off > 0; off >>= 1) {
            s0 += __shfl_xor_sync(0xffffffffu, s0, off);
            s1 += __shfl_xor_sync(0xffffffffu, s1, off);
        }
        if (lane == 0) {
            out[base + m]     = s0;
            out[base + m + 8] = s1;
        }
    }
    if (m < len) {
        float4 a0 = xb[(size_t)m * 64 + lane];
        float4 a1 = xb[(size_t)m * 64 + 32 + lane];
        float s0 = 0.f;
        s0 = fmaf(a0.x, v0.x, s0); s0 = fmaf(a0.y, v0.y, s0);
        s0 = fmaf(a0.z, v0.z, s0); s0 = fmaf(a0.w, v0.w, s0);
        s0 = fmaf(a1.x, v1.x, s0); s0 = fmaf(a1.y, v1.y, s0);
        s0 = fmaf(a1.z, v1.z, s0); s0 = fmaf(a1.w, v1.w, s0);
#pragma unroll
        for (int off = 16; off > 0; off >>= 1)
            s0 += __shfl_xor_sync(0xffffffffu, s0, off);
        if (lane == 0) out[base + m] = s0;
    }
}

extern "C" void kernel_launch(void* const* d_in, const int* in_sizes, int n_in,
                              void* d_out, int out_size) {
    const float* xss  = (const float*)d_in[0];
    const float* Wk   = (const float*)d_in[1];
    const float* Wc   = (const float*)d_in[2];
    const float* proj = (const float*)d_in[3];
    const int*   seq  = (const int*)d_in[4];
    float* out = (float*)d_out;

    scan_kernel<<<1, 1024>>>(seq);
    wcomb_kernel<<<DIM_Q, DIM_C>>>(Wk, Wc, proj);
    xsum_kernel<<<DIM_B, 256>>>(xss, seq);
    vgemm_kernel<<<DIM_B / VGB, 256>>>();
    y_kernel<<<DIM_B, 256>>>(xss, seq, out);
}